// round 9
// baseline (speedup 1.0000x reference)
#include <cuda_runtime.h>
#include <math.h>
#include <stdint.h>

#define NTOK 8192
#define DMODEL 512
#define HID 2048
#define CAP 16384
#define PD 588
#define PDP 608
#define STR 36          // A smem row stride / BT1 B row stride
#define STRN 136        // BT0 B smem row stride
#define DSMEM2 73728    // 18432 floats

__device__ float g_patches[(size_t)NTOK * PDP];
__device__ float g_e[(size_t)NTOK * DMODEL];
__device__ float g_ln[(size_t)NTOK * DMODEL];
__device__ float g_q[(size_t)NTOK * DMODEL];
__device__ float g_k[(size_t)NTOK * DMODEL];
__device__ float g_v[(size_t)NTOK * DMODEL];
__device__ float g_attn[(size_t)65536 * 256];
__device__ float g_ctx[(size_t)NTOK * DMODEL];
__device__ float g_e2[(size_t)NTOK * DMODEL];
__device__ float g_xm[(size_t)NTOK * DMODEL];
__device__ float g_H[(size_t)CAP * HID];
__device__ float g_Y[(size_t)CAP * DMODEL];
__device__ float g_o1[(size_t)NTOK * DMODEL];
__device__ float g_o2[(size_t)NTOK * DMODEL];
__device__ float g_pewp[PDP * 512];
__device__ int g_lists[8 * CAP];
__device__ float g_gates[CAP];
__device__ int g_counts[16];
__device__ float g_imp[16];

__device__ __forceinline__ float gelu_f(float v) {
    return 0.5f * v * (1.0f + erff(v * 0.7071067811865476f));
}
__device__ __forceinline__ void split_tf32(float v, float& h, float& l) {
    h = __uint_as_float(__float_as_uint(v) & 0xFFFFE000u);
    float d = v - h;
    uint32_t lb;
    asm("cvt.rna.tf32.f32 %0, %1;" : "=r"(lb) : "f"(d));
    l = __uint_as_float(lb);
}
__device__ __forceinline__ void mma8(float* c, const uint32_t* a, const uint32_t* b) {
    asm volatile(
        "mma.sync.aligned.m16n8k8.row.col.f32.tf32.tf32.f32 "
        "{%0,%1,%2,%3}, {%4,%5,%6,%7}, {%8,%9}, {%0,%1,%2,%3};"
        : "+f"(c[0]), "+f"(c[1]), "+f"(c[2]), "+f"(c[3])
        : "r"(a[0]), "r"(a[1]), "r"(a[2]), "r"(a[3]), "r"(b[0]), "r"(b[1]));
}

__global__ void zero_k() {
    int t = threadIdx.x;
    if (t < 16) { g_counts[t] = 0; g_imp[t] = 0.f; }
}

__global__ void patchify_k(const float* __restrict__ x) {
    long t = (long)blockIdx.x * 256 + threadIdx.x;
    if (t >= (long)NTOK * PDP) return;
    int p = (int)(t % PDP);
    long token = t / PDP;
    if (p >= PD) { g_patches[t] = 0.f; return; }
    int b = (int)(token >> 8), s = (int)(token & 255);
    int hh = s >> 4, ww = s & 15;
    int c = p % 3, pp = p / 3;
    int p1 = pp / 14, p2 = pp % 14;
    g_patches[t] = x[(((long)b * 3 + c) * 224 + hh * 14 + p1) * 224 + ww * 14 + p2];
}

__global__ void padpe_k(const float* __restrict__ w) {
    int t = blockIdx.x * 256 + threadIdx.x;
    if (t >= PDP * 512) return;
    int k = t / 512, n = t % 512;
    g_pewp[t] = (k < PD) ? w[k * 512 + n] : 0.f;
}

// ------------- 3xTF32 mma.sync GEMM, C tile 128x128 -------------------------
// BT=0: B stored [K, n_tot] row-major (ldb = n_tot). BT=1: B stored [n_tot, K] (ldb = row stride).
// EPI 0 dense+bias | 1 +extra[m*512+n] | 2 +extra[(m&255)*512+n]
// EPI 3 gather(ent>>1), gelu | 4 gather(ent), *gate | 5 attn scores (*0.125, per-z head offs)
template<int EPI, int BT>
__global__ __launch_bounds__(256, 1)
void gemm_mma(const float* __restrict__ A, int lda, const float* __restrict__ Bt, int ldb,
              float* __restrict__ C, int ldc, int K, int n_tot,
              const float* __restrict__ bias, const float* __restrict__ extra, int layer)
{
    extern __shared__ float sm[];
    __shared__ int rows_s[128];
    float* sAh = sm;
    float* sAl = sm + 4608;
    float* sBh = sm + 9216;
    float* sBl = sm + 13824;

    int tid = threadIdx.x, lane = tid & 31, w = tid >> 5;
    int m0 = blockIdx.x * 128, n0 = blockIdx.y * 128, e = blockIdx.z;

    if (EPI == 5) {
        int b = e >> 3, h = e & 7;
        A  += (size_t)b * 131072 + h * 64;
        Bt += (size_t)b * 131072 + h * 64;
        C  += (size_t)e * 65536;
    }
    if (EPI == 3 || EPI == 4) {
        int cnt = g_counts[layer * 8 + e];
        if (m0 >= cnt) return;
        Bt += (size_t)e * (size_t)K * n_tot;
        bias += (size_t)e * n_tot;
        if (tid < 128) rows_s[tid] = (m0 + tid < cnt) ? g_lists[e * CAP + m0 + tid] : -1;
        __syncthreads();
    }

    // A loader: row ar, 16 cols at aco
    int ar = tid >> 1, aco = (tid & 1) * 16;
    const float* arow; bool aval = true;
    if (EPI == 3) { int ent = rows_s[ar]; aval = (ent >= 0); arow = A + (size_t)(aval ? (ent >> 1) : 0) * lda; }
    else if (EPI == 4) { int ent = rows_s[ar]; aval = (ent >= 0); arow = A + (size_t)(aval ? ent : 0) * lda; }
    else arow = A + (size_t)(m0 + ar) * lda;

    // B loader
    int bkr = tid >> 5, bnc = (tid & 31) * 4;            // BT0
    const float* brow = Bt + (size_t)(n0 + ar) * ldb;    // BT1 (row per thread)
    const float* bcol = Bt + n0 + bnc;                   // BT0 (col base)

    int wm = (w >> 2) * 64, wn = (w & 3) * 32;

    float acc[4][4][4];
    #pragma unroll
    for (int f = 0; f < 4; f++)
        #pragma unroll
        for (int g = 0; g < 4; g++)
            #pragma unroll
            for (int i = 0; i < 4; i++) acc[f][g][i] = 0.f;

    float4 av[4], bv[4];
    #pragma unroll
    for (int jj = 0; jj < 4; jj++) {
        av[jj] = aval ? *(const float4*)&arow[aco + jj * 4] : make_float4(0.f, 0.f, 0.f, 0.f);
        if (BT == 1) bv[jj] = *(const float4*)&brow[aco + jj * 4];
        else         bv[jj] = *(const float4*)&bcol[(size_t)(bkr + 8 * jj) * ldb];
    }

    const uint32_t* uAh = (const uint32_t*)sAh;
    const uint32_t* uAl = (const uint32_t*)sAl;
    const uint32_t* uBh = (const uint32_t*)sBh;
    const uint32_t* uBl = (const uint32_t*)sBl;

    int NC = K / 32;
    for (int c = 0; c < NC; c++) {
        __syncthreads();
        #pragma unroll
        for (int jj = 0; jj < 4; jj++) {
            float4 ah, al, bh, bl;
            split_tf32(av[jj].x, ah.x, al.x); split_tf32(av[jj].y, ah.y, al.y);
            split_tf32(av[jj].z, ah.z, al.z); split_tf32(av[jj].w, ah.w, al.w);
            split_tf32(bv[jj].x, bh.x, bl.x); split_tf32(bv[jj].y, bh.y, bl.y);
            split_tf32(bv[jj].z, bh.z, bl.z); split_tf32(bv[jj].w, bh.w, bl.w);
            *(float4*)&sAh[ar * STR + aco + 4 * jj] = ah;
            *(float4*)&sAl[ar * STR + aco + 4 * jj] = al;
            if (BT == 1) {
                *(float4*)&sBh[ar * STR + aco + 4 * jj] = bh;
                *(float4*)&sBl[ar * STR + aco + 4 * jj] = bl;
            } else {
                *(float4*)&sBh[(bkr + 8 * jj) * STRN + bnc] = bh;
                *(float4*)&sBl[(bkr + 8 * jj) * STRN + bnc] = bl;
            }
        }
        __syncthreads();
        if (c + 1 < NC) {
            #pragma unroll
            for (int jj = 0; jj < 4; jj++) {
                av[jj] = aval ? *(const float4*)&arow[(c + 1) * 32 + aco + jj * 4]
                              : make_float4(0.f, 0.f, 0.f, 0.f);
                if (BT == 1) bv[jj] = *(const float4*)&brow[(c + 1) * 32 + aco + jj * 4];
                else         bv[jj] = *(const float4*)&bcol[(size_t)((c + 1) * 32 + bkr + 8 * jj) * ldb];
            }
        }
        #pragma unroll
        for (int s = 0; s < 4; s++) {
            int k0 = s * 8;
            uint32_t ahf[4][4], alf[4][4], bhf[4][2], blf[4][2];
            #pragma unroll
            for (int f = 0; f < 4; f++) {
                int arr = wm + 16 * f + (lane >> 2);
                int acn = k0 + (lane & 3);
                ahf[f][0] = uAh[arr * STR + acn];
                ahf[f][1] = uAh[(arr + 8) * STR + acn];
                ahf[f][2] = uAh[arr * STR + acn + 4];
                ahf[f][3] = uAh[(arr + 8) * STR + acn + 4];
                alf[f][0] = uAl[arr * STR + acn];
                alf[f][1] = uAl[(arr + 8) * STR + acn];
                alf[f][2] = uAl[arr * STR + acn + 4];
                alf[f][3] = uAl[(arr + 8) * STR + acn + 4];
            }
            #pragma unroll
            for (int g = 0; g < 4; g++) {
                if (BT == 1) {
                    int brr = wn + 8 * g + (lane >> 2);
                    int bcn = k0 + (lane & 3);
                    bhf[g][0] = uBh[brr * STR + bcn];
                    bhf[g][1] = uBh[brr * STR + bcn + 4];
                    blf[g][0] = uBl[brr * STR + bcn];
                    blf[g][1] = uBl[brr * STR + bcn + 4];
                } else {
                    int idx = (k0 + (lane & 3)) * STRN + wn + 8 * g + (lane >> 2);
                    bhf[g][0] = uBh[idx];
                    bhf[g][1] = uBh[idx + 4 * STRN];
                    blf[g][0] = uBl[idx];
                    blf[g][1] = uBl[idx + 4 * STRN];
                }
            }
            #pragma unroll
            for (int f = 0; f < 4; f++)
                #pragma unroll
                for (int g = 0; g < 4; g++) {
                    mma8(acc[f][g], ahf[f], bhf[g]);
                    mma8(acc[f][g], ahf[f], blf[g]);
                    mma8(acc[f][g], alf[f], bhf[g]);
                }
        }
    }

    #pragma unroll
    for (int f = 0; f < 4; f++) {
        int row0 = wm + 16 * f + (lane >> 2);
        #pragma unroll
        for (int g = 0; g < 4; g++) {
            int ncol = wn + 8 * g + 2 * (lane & 3);
            int n = n0 + ncol;
            #pragma unroll
            for (int hh = 0; hh < 2; hh++) {
                int mloc = row0 + hh * 8;
                float v0, v1;
                if (EPI == 5) {
                    v0 = acc[f][g][hh * 2] * 0.125f;
                    v1 = acc[f][g][hh * 2 + 1] * 0.125f;
                    *(float2*)&C[(size_t)(m0 + mloc) * ldc + n] = make_float2(v0, v1);
                    continue;
                }
                v0 = acc[f][g][hh * 2] + bias[n];
                v1 = acc[f][g][hh * 2 + 1] + bias[n + 1];
                if (EPI <= 2) {
                    size_t m = (size_t)(m0 + mloc);
                    if (EPI == 1) {
                        const float* ex = extra + m * 512 + n;
                        v0 += ex[0]; v1 += ex[1];
                    }
                    if (EPI == 2) {
                        const float* ex = extra + (size_t)((m0 + mloc) & 255) * 512 + n;
                        v0 += ex[0]; v1 += ex[1];
                    }
                    *(float2*)&C[m * ldc + n] = make_float2(v0, v1);
                } else {
                    int ent = rows_s[mloc];
                    if (ent >= 0) {
                        if (EPI == 3) { v0 = gelu_f(v0); v1 = gelu_f(v1); }
                        else { float gt = g_gates[ent]; v0 *= gt; v1 *= gt; }
                        *(float2*)&C[(size_t)ent * ldc + n] = make_float2(v0, v1);
                    }
                }
            }
        }
    }
}

// ---------------- small SIMT GEMM (cls head) --------------------------------
__global__ __launch_bounds__(256)
void gemm_nn(const float* __restrict__ A, const float* __restrict__ B,
             float* __restrict__ C, int M, int N, int K, const float* __restrict__ bias)
{
    __shared__ float As[16][65], Bs[16][65];
    int tid = threadIdx.x, tx = tid & 15, ty = tid >> 4;
    int m0 = blockIdx.x * 64, n0 = blockIdx.y * 64;
    float acc[4][4] = {};
    for (int kk = 0; kk < K; kk += 16) {
        #pragma unroll
        for (int i = 0; i < 4; i++) {
            int idx = tid + i * 256, rr = idx >> 4, cc = idx & 15;
            As[cc][rr] = (m0 + rr < M) ? A[(long)(m0 + rr) * K + kk + cc] : 0.f;
        }
        #pragma unroll
        for (int i = 0; i < 4; i++) {
            int idx = tid + i * 256, rr = idx >> 6, cc = idx & 63;
            Bs[rr][cc] = B[(long)(kk + rr) * N + n0 + cc];
        }
        __syncthreads();
        #pragma unroll
        for (int k = 0; k < 16; k++) {
            float a[4], b[4];
            #pragma unroll
            for (int i = 0; i < 4; i++) a[i] = As[k][ty * 4 + i];
            #pragma unroll
            for (int j = 0; j < 4; j++) b[j] = Bs[k][tx * 4 + j];
            #pragma unroll
            for (int i = 0; i < 4; i++)
                #pragma unroll
                for (int j = 0; j < 4; j++) acc[i][j] = fmaf(a[i], b[j], acc[i][j]);
        }
        __syncthreads();
    }
    #pragma unroll
    for (int i = 0; i < 4; i++) {
        int m = m0 + ty * 4 + i;
        if (m >= M) continue;
        #pragma unroll
        for (int j = 0; j < 4; j++) {
            int n = n0 + tx * 4 + j;
            C[(long)m * N + n] = acc[i][j] + bias[n];
        }
    }
}

__global__ __launch_bounds__(256)
void layernorm_k(const float* __restrict__ X, const float* __restrict__ g,
                 const float* __restrict__ bb, float* __restrict__ Y)
{
    __shared__ float red[8];
    __shared__ float mean_s, inv_s;
    long row = blockIdx.x;
    const float* x = X + row * DMODEL;
    int t = threadIdx.x;
    float v0 = x[t], v1 = x[t + 256];
    float s = v0 + v1;
    #pragma unroll
    for (int o = 16; o; o >>= 1) s += __shfl_down_sync(0xffffffffu, s, o);
    if ((t & 31) == 0) red[t >> 5] = s;
    __syncthreads();
    if (t == 0) {
        float q = 0.f;
        #pragma unroll
        for (int w = 0; w < 8; w++) q += red[w];
        mean_s = q * (1.f / DMODEL);
    }
    __syncthreads();
    float mean = mean_s;
    float d0 = v0 - mean, d1 = v1 - mean;
    float s2 = d0 * d0 + d1 * d1;
    #pragma unroll
    for (int o = 16; o; o >>= 1) s2 += __shfl_down_sync(0xffffffffu, s2, o);
    if ((t & 31) == 0) red[t >> 5] = s2;
    __syncthreads();
    if (t == 0) {
        float q = 0.f;
        #pragma unroll
        for (int w = 0; w < 8; w++) q += red[w];
        inv_s = rsqrtf(q * (1.f / DMODEL) + 1e-5f);
    }
    __syncthreads();
    float inv = inv_s;
    Y[row * DMODEL + t] = d0 * inv * g[t] + bb[t];
    Y[row * DMODEL + t + 256] = d1 * inv * g[t + 256] + bb[t + 256];
}

__global__ __launch_bounds__(256)
void softmax256_k(float* __restrict__ S)
{
    __shared__ float red[8];
    __shared__ float mx_s, sum_s;
    long row = blockIdx.x;
    float* p = S + row * 256;
    int t = threadIdx.x;
    float v = p[t], m = v;
    #pragma unroll
    for (int o = 16; o; o >>= 1) m = fmaxf(m, __shfl_xor_sync(0xffffffffu, m, o));
    if ((t & 31) == 0) red[t >> 5] = m;
    __syncthreads();
    if (t == 0) {
        float q = red[0];
        #pragma unroll
        for (int w = 1; w < 8; w++) q = fmaxf(q, red[w]);
        mx_s = q;
    }
    __syncthreads();
    float ex = expf(v - mx_s), s = ex;
    #pragma unroll
    for (int o = 16; o; o >>= 1) s += __shfl_xor_sync(0xffffffffu, s, o);
    if ((t & 31) == 0) red[t >> 5] = s;
    __syncthreads();
    if (t == 0) {
        float q = 0.f;
        #pragma unroll
        for (int w = 0; w < 8; w++) q += red[w];
        sum_s = q;
    }
    __syncthreads();
    p[t] = ex / sum_s;
}

__global__ __launch_bounds__(256)
void attn_ctx_k(const float* __restrict__ V)
{
    int bh = blockIdx.y, b = bh >> 3, h = bh & 7;
    const float* A = g_attn + (long)bh * 65536;
    int m0 = blockIdx.x * 64;
    __shared__ float As[16][65], Bs[16][65];
    int tid = threadIdx.x, tx = tid & 15, ty = tid >> 4;
    float acc[4][4] = {};
    for (int kk = 0; kk < 256; kk += 16) {
        #pragma unroll
        for (int i = 0; i < 4; i++) {
            int idx = tid + i * 256, rr = idx >> 4, cc = idx & 15;
            As[cc][rr] = A[(long)(m0 + rr) * 256 + kk + cc];
        }
        #pragma unroll
        for (int i = 0; i < 4; i++) {
            int idx = tid + i * 256, rr = idx >> 6, cc = idx & 63;
            Bs[rr][cc] = V[((long)b * 256 + kk + rr) * 512 + h * 64 + cc];
        }
        __syncthreads();
        #pragma unroll
        for (int k = 0; k < 16; k++) {
            float a[4], bv[4];
            #pragma unroll
            for (int i = 0; i < 4; i++) a[i] = As[k][ty * 4 + i];
            #pragma unroll
            for (int j = 0; j < 4; j++) bv[j] = Bs[k][tx * 4 + j];
            #pragma unroll
            for (int i = 0; i < 4; i++)
                #pragma unroll
                for (int j = 0; j < 4; j++) acc[i][j] = fmaf(a[i], bv[j], acc[i][j]);
        }
        __syncthreads();
    }
    #pragma unroll
    for (int i = 0; i < 4; i++)
        #pragma unroll
        for (int j = 0; j < 4; j++)
            g_ctx[((long)b * 256 + m0 + ty * 4 + i) * 512 + h * 64 + tx * 4 + j] = acc[i][j];
}

__global__ __launch_bounds__(256)
void attn_mean_k(float* __restrict__ out)
{
    __shared__ float red[8];
    __shared__ float mx_s, sum_s;
    int row = blockIdx.x, b = row >> 8, q = row & 255;
    int t = threadIdx.x;
    float s = 0.f;
    #pragma unroll
    for (int h = 0; h < 8; h++) s += g_attn[(((long)(b * 8 + h)) * 256 + q) * 256 + t];
    s *= 0.125f;
    float m = s;
    #pragma unroll
    for (int o = 16; o; o >>= 1) m = fmaxf(m, __shfl_xor_sync(0xffffffffu, m, o));
    if ((t & 31) == 0) red[t >> 5] = m;
    __syncthreads();
    if (t == 0) {
        float q2 = red[0];
        #pragma unroll
        for (int w = 1; w < 8; w++) q2 = fmaxf(q2, red[w]);
        mx_s = q2;
    }
    __syncthreads();
    float ex = expf(s - mx_s), ss = ex;
    #pragma unroll
    for (int o = 16; o; o >>= 1) ss += __shfl_xor_sync(0xffffffffu, ss, o);
    if ((t & 31) == 0) red[t >> 5] = ss;
    __syncthreads();
    if (t == 0) {
        float q2 = 0.f;
        #pragma unroll
        for (int w = 0; w < 8; w++) q2 += red[w];
        sum_s = q2;
    }
    __syncthreads();
    out[(long)row * 256 + t] = ex / sum_s;
}

__global__ __launch_bounds__(256)
void router_k(const float* __restrict__ X, const float* __restrict__ rw,
              const float* __restrict__ rb, int layer)
{
    int warp = (blockIdx.x * blockDim.x + threadIdx.x) >> 5;
    int lane = threadIdx.x & 31;
    if (warp >= NTOK) return;
    const float* x = X + (long)warp * DMODEL;
    float l[8] = {0,0,0,0,0,0,0,0};
    for (int k = lane; k < DMODEL; k += 32) {
        float xv = x[k];
        const float* rr = rw + k * 8;
        #pragma unroll
        for (int e = 0; e < 8; e++) l[e] = fmaf(xv, rr[e], l[e]);
    }
    #pragma unroll
    for (int e = 0; e < 8; e++)
        #pragma unroll
        for (int o = 16; o; o >>= 1) l[e] += __shfl_down_sync(0xffffffffu, l[e], o);
    if (lane == 0) {
        float p[8], mx = -1e30f;
        #pragma unroll
        for (int e = 0; e < 8; e++) { p[e] = l[e] + rb[e]; mx = fmaxf(mx, p[e]); }
        float s = 0.f;
        #pragma unroll
        for (int e = 0; e < 8; e++) { p[e] = expf(p[e] - mx); s += p[e]; }
        float inv = 1.f / s;
        #pragma unroll
        for (int e = 0; e < 8; e++) p[e] *= inv;
        int i1 = 0;
        #pragma unroll
        for (int e = 1; e < 8; e++) if (p[e] > p[i1]) i1 = e;
        int i2 = -1;
        #pragma unroll
        for (int e = 0; e < 8; e++) {
            if (e == i1) continue;
            if (i2 < 0 || p[e] > p[i2]) i2 = e;
        }
        #pragma unroll
        for (int e = 0; e < 8; e++) atomicAdd(&g_imp[layer * 8 + e], p[e]);
        g_gates[2 * warp] = p[i1];
        g_gates[2 * warp + 1] = p[i2];
        int q1 = atomicAdd(&g_counts[layer * 8 + i1], 1);
        g_lists[i1 * CAP + q1] = 2 * warp;
        int q2 = atomicAdd(&g_counts[layer * 8 + i2], 1);
        g_lists[i2 * CAP + q2] = 2 * warp + 1;
    }
}

__global__ void moe_combine_k(float* __restrict__ O)
{
    long i = (long)blockIdx.x * 256 + threadIdx.x;
    long tok = i >> 9; int d = (int)(i & 511);
    O[i] = g_Y[(tok * 2) * DMODEL + d] + g_Y[(tok * 2 + 1) * DMODEL + d];
}

// 2-stage mean pool (deterministic)
__global__ void meanpool1_k(const float* __restrict__ X, float* __restrict__ part)
{
    int b = blockIdx.x, gg = blockIdx.y, t = threadIdx.x;
    #pragma unroll
    for (int j = 0; j < 2; j++) {
        int d = t + j * 256;
        float s = 0.f;
        #pragma unroll 4
        for (int i = 0; i < 32; i++)
            s += X[((size_t)b * 256 + gg * 32 + i) * 512 + d];
        part[((size_t)b * 8 + gg) * 512 + d] = s;
    }
}
__global__ void meanpool2_k(const float* __restrict__ part, float* __restrict__ fv)
{
    int b = blockIdx.x, d = threadIdx.x;
    float s = 0.f;
    #pragma unroll
    for (int gg = 0; gg < 8; gg++) s += part[((size_t)b * 8 + gg) * 512 + d];
    fv[b * 512 + d] = s * (1.f / 256.f);
}

__global__ void loss_k(float* __restrict__ out)
{
    float L = 0.f;
    for (int layer = 0; layer < 2; layer++) {
        float s = 0.f;
        for (int e = 0; e < 8; e++)
            s += ((float)g_counts[layer * 8 + e] * (1.f / NTOK)) * (g_imp[layer * 8 + e] * (1.f / NTOK));
        L += 8.f * s;
    }
    out[0] = L;
}

extern "C" void kernel_launch(void* const* d_in, const int* in_sizes, int n_in,
                              void* d_out, int out_size)
{
    const float* x = (const float*)d_in[0];
    const float* pe_w = (const float*)d_in[1];
    const float* pe_b = (const float*)d_in[2];
    const float* pos = (const float*)d_in[3];
    const float* ln1_g = (const float*)d_in[4]; const float* ln1_b = (const float*)d_in[5];
    const float* ln2_g = (const float*)d_in[6]; const float* ln2_b = (const float*)d_in[7];
    const float* ln3_g = (const float*)d_in[8]; const float* ln3_b = (const float*)d_in[9];
    const float* wq = (const float*)d_in[10]; const float* bq = (const float*)d_in[11];
    const float* wk = (const float*)d_in[12]; const float* bk = (const float*)d_in[13];
    const float* wv = (const float*)d_in[14]; const float* bv = (const float*)d_in[15];
    const float* wo = (const float*)d_in[16]; const float* bo = (const float*)d_in[17];
    const float* m1_rw = (const float*)d_in[18]; const float* m1_rb = (const float*)d_in[19];
    const float* m1_w1 = (const float*)d_in[20]; const float* m1_b1 = (const float*)d_in[21];
    const float* m1_w2 = (const float*)d_in[22]; const float* m1_b2 = (const float*)d_in[23];
    const float* m2_rw = (const float*)d_in[24]; const float* m2_rb = (const float*)d_in[25];
    const float* m2_w1 = (const float*)d_in[26]; const float* m2_b1 = (const float*)d_in[27];
    const float* m2_w2 = (const float*)d_in[28]; const float* m2_b2 = (const float*)d_in[29];
    const float* cls_w = (const float*)d_in[30]; const float* cls_b = (const float*)d_in[31];
    float* out = (float*)d_out;

    cudaFuncSetAttribute(gemm_mma<0,0>, cudaFuncAttributeMaxDynamicSharedMemorySize, DSMEM2);
    cudaFuncSetAttribute(gemm_mma<1,0>, cudaFuncAttributeMaxDynamicSharedMemorySize, DSMEM2);
    cudaFuncSetAttribute(gemm_mma<2,0>, cudaFuncAttributeMaxDynamicSharedMemorySize, DSMEM2);
    cudaFuncSetAttribute(gemm_mma<3,0>, cudaFuncAttributeMaxDynamicSharedMemorySize, DSMEM2);
    cudaFuncSetAttribute(gemm_mma<4,0>, cudaFuncAttributeMaxDynamicSharedMemorySize, DSMEM2);
    cudaFuncSetAttribute(gemm_mma<5,1>, cudaFuncAttributeMaxDynamicSharedMemorySize, DSMEM2);

    void *pP, *pE, *pL, *pQ, *pK, *pV, *pC, *pE2, *pX, *pO1, *pO2, *pA, *pH, *pY, *pPE;
    cudaGetSymbolAddress(&pP, g_patches); cudaGetSymbolAddress(&pE, g_e);
    cudaGetSymbolAddress(&pL, g_ln); cudaGetSymbolAddress(&pQ, g_q);
    cudaGetSymbolAddress(&pK, g_k); cudaGetSymbolAddress(&pV, g_v);
    cudaGetSymbolAddress(&pC, g_ctx); cudaGetSymbolAddress(&pE2, g_e2);
    cudaGetSymbolAddress(&pX, g_xm); cudaGetSymbolAddress(&pO1, g_o1);
    cudaGetSymbolAddress(&pO2, g_o2); cudaGetSymbolAddress(&pA, g_attn);
    cudaGetSymbolAddress(&pH, g_H); cudaGetSymbolAddress(&pY, g_Y);
    cudaGetSymbolAddress(&pPE, g_pewp);

    float* logits_out = out;
    float* fv_out = out + 16384;
    float* loss_out = out + 32768;
    float* attnw_out = out + 32769;

    zero_k<<<1, 32>>>();
    patchify_k<<<(NTOK * PDP + 255) / 256, 256>>>(x);
    padpe_k<<<(PDP * 512 + 255) / 256, 256>>>(pe_w);

    gemm_mma<2,0><<<dim3(64, 4), 256, DSMEM2>>>((const float*)pP, PDP, (const float*)pPE, 512,
                                                (float*)pE, 512, PDP, 512, pe_b, pos, 0);
    layernorm_k<<<NTOK, 256>>>((const float*)pE, ln1_g, ln1_b, (float*)pL);
    gemm_mma<0,0><<<dim3(64, 4), 256, DSMEM2>>>((const float*)pL, 512, wq, 512,
                                                (float*)pQ, 512, 512, 512, bq, nullptr, 0);
    gemm_mma<0,0><<<dim3(64, 4), 256, DSMEM2>>>((const float*)pL, 512, wk, 512,
                                                (float*)pK, 512, 512, 512, bk, nullptr, 0);
    gemm_mma<0,0><<<dim3(64, 4), 256, DSMEM2>>>((const float*)pL, 512, wv, 512,
                                                (float*)pV, 512, 512, 512, bv, nullptr, 0);
    gemm_mma<5,1><<<dim3(2, 2, 256), 256, DSMEM2>>>((const float*)pQ, 512, (const float*)pK, 512,
                                                    (float*)pA, 256, 64, 256, nullptr, nullptr, 0);
    softmax256_k<<<65536, 256>>>((float*)pA);
    attn_mean_k<<<NTOK, 256>>>(attnw_out);
    attn_ctx_k<<<dim3(4, 256), 256>>>((const float*)pV);
    gemm_mma<1,0><<<dim3(64, 4), 256, DSMEM2>>>((const float*)pC, 512, wo, 512,
                                                (float*)pE2, 512, 512, 512, bo, (const float*)pE, 0);

    // MoE layer 1
    layernorm_k<<<NTOK, 256>>>((const float*)pE2, ln2_g, ln2_b, (float*)pX);
    router_k<<<NTOK / 8, 256>>>((const float*)pX, m1_rw, m1_rb, 0);
    gemm_mma<3,0><<<dim3(128, 16, 8), 256, DSMEM2>>>((const float*)pX, 512, m1_w1, 2048,
                                                     (float*)pH, 2048, 512, 2048, m1_b1, nullptr, 0);
    gemm_mma<4,0><<<dim3(128, 4, 8), 256, DSMEM2>>>((const float*)pH, 2048, m1_w2, 512,
                                                    (float*)pY, 512, 2048, 512, m1_b2, nullptr, 0);
    moe_combine_k<<<NTOK * DMODEL / 256, 256>>>((float*)pO1);

    // MoE layer 2
    layernorm_k<<<NTOK, 256>>>((const float*)pO1, ln3_g, ln3_b, (float*)pX);
    router_k<<<NTOK / 8, 256>>>((const float*)pX, m2_rw, m2_rb, 1);
    gemm_mma<3,0><<<dim3(128, 16, 8), 256, DSMEM2>>>((const float*)pX, 512, m2_w1, 2048,
                                                     (float*)pH, 2048, 512, 2048, m2_b1, nullptr, 1);
    gemm_mma<4,0><<<dim3(128, 4, 8), 256, DSMEM2>>>((const float*)pH, 2048, m2_w2, 512,
                                                    (float*)pY, 512, 2048, 512, m2_b2, nullptr, 1);
    moe_combine_k<<<NTOK * DMODEL / 256, 256>>>((float*)pO2);

    meanpool1_k<<<dim3(32, 8), 256>>>((const float*)pO2, (float*)pP);
    meanpool2_k<<<32, 512>>>((const float*)pP, fv_out);
    gemm_nn<<<dim3(1, 8), 256>>>(fv_out, cls_w, logits_out, 32, 512, 512, cls_b);
    loss_k<<<1, 1>>>(loss_out);
}

// round 10
// speedup vs baseline: 1.6040x; 1.6040x over previous
#include <cuda_runtime.h>
#include <math.h>
#include <stdint.h>

#define NTOK 8192
#define DMODEL 512
#define HID 2048
#define CAP 16384
#define PD 588
#define PDP 608
#define STR 36
#define DSMEM2 73728

__device__ float g_patches[(size_t)NTOK * PDP];
__device__ float g_e[(size_t)NTOK * DMODEL];
__device__ float g_ln[(size_t)NTOK * DMODEL];
__device__ float g_q[(size_t)NTOK * DMODEL];
__device__ float g_k[(size_t)NTOK * DMODEL];
__device__ float g_v[(size_t)NTOK * DMODEL];
__device__ float g_attn[(size_t)65536 * 256];
__device__ float g_ctx[(size_t)NTOK * DMODEL];
__device__ float g_e2[(size_t)NTOK * DMODEL];
__device__ float g_xm[(size_t)NTOK * DMODEL];
__device__ float g_H[(size_t)CAP * HID];
__device__ float g_Y[(size_t)CAP * DMODEL];
__device__ float g_o1[(size_t)NTOK * DMODEL];
__device__ float g_o2[(size_t)NTOK * DMODEL];
__device__ int g_lists[8 * CAP];
__device__ float g_gates[CAP];
__device__ int g_counts[16];
__device__ float g_imp[16];
__device__ float g_pewt[512 * PDP];
__device__ float g_wqt[512 * 512];
__device__ float g_wkt[512 * 512];
__device__ float g_wvt[512 * 512];
__device__ float g_wot[512 * 512];
__device__ float g_w1t[(size_t)8 * HID * DMODEL];
__device__ float g_w2t[(size_t)8 * DMODEL * HID];

__device__ __forceinline__ float gelu_f(float v) {
    return 0.5f * v * (1.0f + erff(v * 0.7071067811865476f));
}
__device__ __forceinline__ void split_tf32(float v, float& h, float& l) {
    h = __uint_as_float(__float_as_uint(v) & 0xFFFFE000u);
    float d = v - h;
    uint32_t lb;
    asm("cvt.rna.tf32.f32 %0, %1;" : "=r"(lb) : "f"(d));
    l = __uint_as_float(lb);
}
__device__ __forceinline__ void mma8(float* c, const uint32_t* a, const uint32_t* b) {
    asm volatile(
        "mma.sync.aligned.m16n8k8.row.col.f32.tf32.tf32.f32 "
        "{%0,%1,%2,%3}, {%4,%5,%6,%7}, {%8,%9}, {%0,%1,%2,%3};"
        : "+f"(c[0]), "+f"(c[1]), "+f"(c[2]), "+f"(c[3])
        : "r"(a[0]), "r"(a[1]), "r"(a[2]), "r"(a[3]), "r"(b[0]), "r"(b[1]));
}

__global__ void zero_k() {
    int t = threadIdx.x;
    if (t < 16) { g_counts[t] = 0; g_imp[t] = 0.f; }
}

__global__ void patchify_k(const float* __restrict__ x) {
    long t = (long)blockIdx.x * 256 + threadIdx.x;
    if (t >= (long)NTOK * PDP) return;
    int p = (int)(t % PDP);
    long token = t / PDP;
    if (p >= PD) { g_patches[t] = 0.f; return; }
    int b = (int)(token >> 8), s = (int)(token & 255);
    int hh = s >> 4, ww = s & 15;
    int c = p % 3, pp = p / 3;
    int p1 = pp / 14, p2 = pp % 14;
    g_patches[t] = x[(((long)b * 3 + c) * 224 + hh * 14 + p1) * 224 + ww * 14 + p2];
}

// in[R,C] (z-batched) -> out[C,Rpad], zero-pad rows >= R
__global__ __launch_bounds__(256)
void transpose_k(const float* __restrict__ in, float* __restrict__ out, int R, int Cc, int Rpad)
{
    __shared__ float t[32][33];
    int z = blockIdx.z;
    in  += (size_t)z * R * Cc;
    out += (size_t)z * Cc * Rpad;
    int r0 = blockIdx.x * 32, c0 = blockIdx.y * 32;
    int tx = threadIdx.x & 31, ty = threadIdx.x >> 5;
    #pragma unroll
    for (int i = 0; i < 4; i++) {
        int rr = r0 + ty + i * 8;
        t[ty + i * 8][tx] = (rr < R) ? in[(size_t)rr * Cc + c0 + tx] : 0.f;
    }
    __syncthreads();
    #pragma unroll
    for (int i = 0; i < 4; i++)
        out[(size_t)(c0 + ty + i * 8) * Rpad + r0 + tx] = t[tx][ty + i * 8];
}

// ------------- 3xTF32 mma.sync GEMM, C tile 128x128, B is [n_tot, K] --------
// EPI 0 dense+bias | 1 +extra[m*512+n] | 2 +extra[(m&255)*512+n]
// EPI 3 gather(ent>>1), gelu | 4 gather(ent), *gate | 5 attn scores (*0.125)
template<int EPI>
__global__ __launch_bounds__(256, 2)
void gemm_mma(const float* __restrict__ A, int lda, const float* __restrict__ Bt, int ldb,
              float* __restrict__ C, int ldc, int K, int n_tot,
              const float* __restrict__ bias, const float* __restrict__ extra, int layer)
{
    extern __shared__ float sm[];
    __shared__ int rows_s[128];
    float* sAh = sm;
    float* sAl = sm + 4608;
    float* sBh = sm + 9216;
    float* sBl = sm + 13824;

    int tid = threadIdx.x, lane = tid & 31, w = tid >> 5;
    int m0 = blockIdx.x * 128, n0 = blockIdx.y * 128, e = blockIdx.z;

    if (EPI == 5) {
        int b = e >> 3, h = e & 7;
        A  += (size_t)b * 131072 + h * 64;
        Bt += (size_t)b * 131072 + h * 64;
        C  += (size_t)e * 65536;
    }
    if (EPI == 3 || EPI == 4) {
        int cnt = g_counts[layer * 8 + e];
        if (m0 >= cnt) return;
        Bt += (size_t)e * (size_t)n_tot * K;
        bias += (size_t)e * n_tot;
        if (tid < 128) rows_s[tid] = (m0 + tid < cnt) ? g_lists[e * CAP + m0 + tid] : -1;
        __syncthreads();
    }

    int ar = tid >> 1, aco = (tid & 1) * 16;
    const float* arow; bool aval = true;
    if (EPI == 3) { int ent = rows_s[ar]; aval = (ent >= 0); arow = A + (size_t)(aval ? (ent >> 1) : 0) * lda; }
    else if (EPI == 4) { int ent = rows_s[ar]; aval = (ent >= 0); arow = A + (size_t)(aval ? ent : 0) * lda; }
    else arow = A + (size_t)(m0 + ar) * lda;
    const float* brow = Bt + (size_t)(n0 + ar) * ldb;

    int wm = (w >> 2) * 64, wn = (w & 3) * 32;

    float acc[4][4][4];
    #pragma unroll
    for (int f = 0; f < 4; f++)
        #pragma unroll
        for (int g = 0; g < 4; g++)
            #pragma unroll
            for (int i = 0; i < 4; i++) acc[f][g][i] = 0.f;

    const uint32_t* uAh = (const uint32_t*)sAh;
    const uint32_t* uAl = (const uint32_t*)sAl;
    const uint32_t* uBh = (const uint32_t*)sBh;
    const uint32_t* uBl = (const uint32_t*)sBl;

    int NC = K / 32;
    for (int c = 0; c < NC; c++) {
        // issue this chunk's global loads BEFORE the barrier: the barrier wait
        // (other warps finishing previous compute) hides the LDG latency.
        float4 av[4], bv[4];
        #pragma unroll
        for (int jj = 0; jj < 4; jj++) {
            av[jj] = aval ? *(const float4*)&arow[c * 32 + aco + jj * 4]
                          : make_float4(0.f, 0.f, 0.f, 0.f);
            bv[jj] = *(const float4*)&brow[c * 32 + aco + jj * 4];
        }
        __syncthreads();
        #pragma unroll
        for (int jj = 0; jj < 4; jj++) {
            float4 ah, al, bh, bl;
            split_tf32(av[jj].x, ah.x, al.x); split_tf32(av[jj].y, ah.y, al.y);
            split_tf32(av[jj].z, ah.z, al.z); split_tf32(av[jj].w, ah.w, al.w);
            split_tf32(bv[jj].x, bh.x, bl.x); split_tf32(bv[jj].y, bh.y, bl.y);
            split_tf32(bv[jj].z, bh.z, bl.z); split_tf32(bv[jj].w, bh.w, bl.w);
            *(float4*)&sAh[ar * STR + aco + 4 * jj] = ah;
            *(float4*)&sAl[ar * STR + aco + 4 * jj] = al;
            *(float4*)&sBh[ar * STR + aco + 4 * jj] = bh;
            *(float4*)&sBl[ar * STR + aco + 4 * jj] = bl;
        }
        __syncthreads();
        #pragma unroll
        for (int s = 0; s < 4; s++) {
            int k0 = s * 8;
            uint32_t ahf[4][4], alf[4][4], bhf[4][2], blf[4][2];
            #pragma unroll
            for (int f = 0; f < 4; f++) {
                int arr = wm + 16 * f + (lane >> 2);
                int acn = k0 + (lane & 3);
                ahf[f][0] = uAh[arr * STR + acn];
                ahf[f][1] = uAh[(arr + 8) * STR + acn];
                ahf[f][2] = uAh[arr * STR + acn + 4];
                ahf[f][3] = uAh[(arr + 8) * STR + acn + 4];
                alf[f][0] = uAl[arr * STR + acn];
                alf[f][1] = uAl[(arr + 8) * STR + acn];
                alf[f][2] = uAl[arr * STR + acn + 4];
                alf[f][3] = uAl[(arr + 8) * STR + acn + 4];
            }
            #pragma unroll
            for (int g = 0; g < 4; g++) {
                int brr = wn + 8 * g + (lane >> 2);
                int bcn = k0 + (lane & 3);
                bhf[g][0] = uBh[brr * STR + bcn];
                bhf[g][1] = uBh[brr * STR + bcn + 4];
                blf[g][0] = uBl[brr * STR + bcn];
                blf[g][1] = uBl[brr * STR + bcn + 4];
            }
            #pragma unroll
            for (int f = 0; f < 4; f++)
                #pragma unroll
                for (int g = 0; g < 4; g++) {
                    mma8(acc[f][g], ahf[f], bhf[g]);
                    mma8(acc[f][g], ahf[f], blf[g]);
                    mma8(acc[f][g], alf[f], bhf[g]);
                }
        }
    }

    #pragma unroll
    for (int f = 0; f < 4; f++) {
        int row0 = wm + 16 * f + (lane >> 2);
        #pragma unroll
        for (int g = 0; g < 4; g++) {
            int ncol = wn + 8 * g + 2 * (lane & 3);
            int n = n0 + ncol;
            #pragma unroll
            for (int hh = 0; hh < 2; hh++) {
                int mloc = row0 + hh * 8;
                float v0, v1;
                if (EPI == 5) {
                    v0 = acc[f][g][hh * 2] * 0.125f;
                    v1 = acc[f][g][hh * 2 + 1] * 0.125f;
                    *(float2*)&C[(size_t)(m0 + mloc) * ldc + n] = make_float2(v0, v1);
                    continue;
                }
                v0 = acc[f][g][hh * 2] + bias[n];
                v1 = acc[f][g][hh * 2 + 1] + bias[n + 1];
                if (EPI <= 2) {
                    size_t m = (size_t)(m0 + mloc);
                    if (EPI == 1) {
                        const float* ex = extra + m * 512 + n;
                        v0 += ex[0]; v1 += ex[1];
                    }
                    if (EPI == 2) {
                        const float* ex = extra + (size_t)((m0 + mloc) & 255) * 512 + n;
                        v0 += ex[0]; v1 += ex[1];
                    }
                    *(float2*)&C[m * ldc + n] = make_float2(v0, v1);
                } else {
                    int ent = rows_s[mloc];
                    if (ent >= 0) {
                        if (EPI == 3) { v0 = gelu_f(v0); v1 = gelu_f(v1); }
                        else { float gt = g_gates[ent]; v0 *= gt; v1 *= gt; }
                        *(float2*)&C[(size_t)ent * ldc + n] = make_float2(v0, v1);
                    }
                }
            }
        }
    }
}

// ---------------- small SIMT GEMM (cls head) --------------------------------
__global__ __launch_bounds__(256)
void gemm_nn(const float* __restrict__ A, const float* __restrict__ B,
             float* __restrict__ C, int M, int N, int K, const float* __restrict__ bias)
{
    __shared__ float As[16][65], Bs[16][65];
    int tid = threadIdx.x, tx = tid & 15, ty = tid >> 4;
    int m0 = blockIdx.x * 64, n0 = blockIdx.y * 64;
    float acc[4][4] = {};
    for (int kk = 0; kk < K; kk += 16) {
        #pragma unroll
        for (int i = 0; i < 4; i++) {
            int idx = tid + i * 256, rr = idx >> 4, cc = idx & 15;
            As[cc][rr] = (m0 + rr < M) ? A[(long)(m0 + rr) * K + kk + cc] : 0.f;
        }
        #pragma unroll
        for (int i = 0; i < 4; i++) {
            int idx = tid + i * 256, rr = idx >> 6, cc = idx & 63;
            Bs[rr][cc] = B[(long)(kk + rr) * N + n0 + cc];
        }
        __syncthreads();
        #pragma unroll
        for (int k = 0; k < 16; k++) {
            float a[4], b[4];
            #pragma unroll
            for (int i = 0; i < 4; i++) a[i] = As[k][ty * 4 + i];
            #pragma unroll
            for (int j = 0; j < 4; j++) b[j] = Bs[k][tx * 4 + j];
            #pragma unroll
            for (int i = 0; i < 4; i++)
                #pragma unroll
                for (int j = 0; j < 4; j++) acc[i][j] = fmaf(a[i], b[j], acc[i][j]);
        }
        __syncthreads();
    }
    #pragma unroll
    for (int i = 0; i < 4; i++) {
        int m = m0 + ty * 4 + i;
        if (m >= M) continue;
        #pragma unroll
        for (int j = 0; j < 4; j++) {
            int n = n0 + tx * 4 + j;
            C[(long)m * N + n] = acc[i][j] + bias[n];
        }
    }
}

__global__ __launch_bounds__(256)
void layernorm_k(const float* __restrict__ X, const float* __restrict__ g,
                 const float* __restrict__ bb, float* __restrict__ Y)
{
    __shared__ float red[8];
    __shared__ float mean_s, inv_s;
    long row = blockIdx.x;
    const float* x = X + row * DMODEL;
    int t = threadIdx.x;
    float v0 = x[t], v1 = x[t + 256];
    float s = v0 + v1;
    #pragma unroll
    for (int o = 16; o; o >>= 1) s += __shfl_down_sync(0xffffffffu, s, o);
    if ((t & 31) == 0) red[t >> 5] = s;
    __syncthreads();
    if (t == 0) {
        float q = 0.f;
        #pragma unroll
        for (int w = 0; w < 8; w++) q += red[w];
        mean_s = q * (1.f / DMODEL);
    }
    __syncthreads();
    float mean = mean_s;
    float d0 = v0 - mean, d1 = v1 - mean;
    float s2 = d0 * d0 + d1 * d1;
    #pragma unroll
    for (int o = 16; o; o >>= 1) s2 += __shfl_down_sync(0xffffffffu, s2, o);
    if ((t & 31) == 0) red[t >> 5] = s2;
    __syncthreads();
    if (t == 0) {
        float q = 0.f;
        #pragma unroll
        for (int w = 0; w < 8; w++) q += red[w];
        inv_s = rsqrtf(q * (1.f / DMODEL) + 1e-5f);
    }
    __syncthreads();
    float inv = inv_s;
    Y[row * DMODEL + t] = d0 * inv * g[t] + bb[t];
    Y[row * DMODEL + t + 256] = d1 * inv * g[t + 256] + bb[t + 256];
}

__global__ __launch_bounds__(256)
void softmax256_k(float* __restrict__ S)
{
    __shared__ float red[8];
    __shared__ float mx_s, sum_s;
    long row = blockIdx.x;
    float* p = S + row * 256;
    int t = threadIdx.x;
    float v = p[t], m = v;
    #pragma unroll
    for (int o = 16; o; o >>= 1) m = fmaxf(m, __shfl_xor_sync(0xffffffffu, m, o));
    if ((t & 31) == 0) red[t >> 5] = m;
    __syncthreads();
    if (t == 0) {
        float q = red[0];
        #pragma unroll
        for (int w = 1; w < 8; w++) q = fmaxf(q, red[w]);
        mx_s = q;
    }
    __syncthreads();
    float ex = expf(v - mx_s), s = ex;
    #pragma unroll
    for (int o = 16; o; o >>= 1) s += __shfl_xor_sync(0xffffffffu, s, o);
    if ((t & 31) == 0) red[t >> 5] = s;
    __syncthreads();
    if (t == 0) {
        float q = 0.f;
        #pragma unroll
        for (int w = 0; w < 8; w++) q += red[w];
        sum_s = q;
    }
    __syncthreads();
    p[t] = ex / sum_s;
}

__global__ __launch_bounds__(256)
void attn_ctx_k(const float* __restrict__ V)
{
    int bh = blockIdx.y, b = bh >> 3, h = bh & 7;
    const float* A = g_attn + (long)bh * 65536;
    int m0 = blockIdx.x * 64;
    __shared__ float As[16][65], Bs[16][65];
    int tid = threadIdx.x, tx = tid & 15, ty = tid >> 4;
    float acc[4][4] = {};
    for (int kk = 0; kk < 256; kk += 16) {
        #pragma unroll
        for (int i = 0; i < 4; i++) {
            int idx = tid + i * 256, rr = idx >> 4, cc = idx & 15;
            As[cc][rr] = A[(long)(m0 + rr) * 256 + kk + cc];
        }
        #pragma unroll
        for (int i = 0; i < 4; i++) {
            int idx = tid + i * 256, rr = idx >> 6, cc = idx & 63;
            Bs[rr][cc] = V[((long)b * 256 + kk + rr) * 512 + h * 64 + cc];
        }
        __syncthreads();
        #pragma unroll
        for (int k = 0; k < 16; k++) {
            float a[4], bv[4];
            #pragma unroll
            for (int i = 0; i < 4; i++) a[i] = As[k][ty * 4 + i];
            #pragma unroll
            for (int j = 0; j < 4; j++) bv[j] = Bs[k][tx * 4 + j];
            #pragma unroll
            for (int i = 0; i < 4; i++)
                #pragma unroll
                for (int j = 0; j < 4; j++) acc[i][j] = fmaf(a[i], bv[j], acc[i][j]);
        }
        __syncthreads();
    }
    #pragma unroll
    for (int i = 0; i < 4; i++)
        #pragma unroll
        for (int j = 0; j < 4; j++)
            g_ctx[((long)b * 256 + m0 + ty * 4 + i) * 512 + h * 64 + tx * 4 + j] = acc[i][j];
}

__global__ __launch_bounds__(256)
void attn_mean_k(float* __restrict__ out)
{
    __shared__ float red[8];
    __shared__ float mx_s, sum_s;
    int row = blockIdx.x, b = row >> 8, q = row & 255;
    int t = threadIdx.x;
    float s = 0.f;
    #pragma unroll
    for (int h = 0; h < 8; h++) s += g_attn[(((long)(b * 8 + h)) * 256 + q) * 256 + t];
    s *= 0.125f;
    float m = s;
    #pragma unroll
    for (int o = 16; o; o >>= 1) m = fmaxf(m, __shfl_xor_sync(0xffffffffu, m, o));
    if ((t & 31) == 0) red[t >> 5] = m;
    __syncthreads();
    if (t == 0) {
        float q2 = red[0];
        #pragma unroll
        for (int w = 1; w < 8; w++) q2 = fmaxf(q2, red[w]);
        mx_s = q2;
    }
    __syncthreads();
    float ex = expf(s - mx_s), ss = ex;
    #pragma unroll
    for (int o = 16; o; o >>= 1) ss += __shfl_xor_sync(0xffffffffu, ss, o);
    if ((t & 31) == 0) red[t >> 5] = ss;
    __syncthreads();
    if (t == 0) {
        float q2 = 0.f;
        #pragma unroll
        for (int w = 0; w < 8; w++) q2 += red[w];
        sum_s = q2;
    }
    __syncthreads();
    out[(long)row * 256 + t] = ex / sum_s;
}

__global__ __launch_bounds__(256)
void router_k(const float* __restrict__ X, const float* __restrict__ rw,
              const float* __restrict__ rb, int layer)
{
    int warp = (blockIdx.x * blockDim.x + threadIdx.x) >> 5;
    int lane = threadIdx.x & 31;
    if (warp >= NTOK) return;
    const float* x = X + (long)warp * DMODEL;
    float l[8] = {0,0,0,0,0,0,0,0};
    for (int k = lane; k < DMODEL; k += 32) {
        float xv = x[k];
        const float* rr = rw + k * 8;
        #pragma unroll
        for (int e = 0; e < 8; e++) l[e] = fmaf(xv, rr[e], l[e]);
    }
    #pragma unroll
    for (int e = 0; e < 8; e++)
        #pragma unroll
        for (int o = 16; o; o >>= 1) l[e] += __shfl_down_sync(0xffffffffu, l[e], o);
    if (lane == 0) {
        float p[8], mx = -1e30f;
        #pragma unroll
        for (int e = 0; e < 8; e++) { p[e] = l[e] + rb[e]; mx = fmaxf(mx, p[e]); }
        float s = 0.f;
        #pragma unroll
        for (int e = 0; e < 8; e++) { p[e] = expf(p[e] - mx); s += p[e]; }
        float inv = 1.f / s;
        #pragma unroll
        for (int e = 0; e < 8; e++) p[e] *= inv;
        int i1 = 0;
        #pragma unroll
        for (int e = 1; e < 8; e++) if (p[e] > p[i1]) i1 = e;
        int i2 = -1;
        #pragma unroll
        for (int e = 0; e < 8; e++) {
            if (e == i1) continue;
            if (i2 < 0 || p[e] > p[i2]) i2 = e;
        }
        #pragma unroll
        for (int e = 0; e < 8; e++) atomicAdd(&g_imp[layer * 8 + e], p[e]);
        g_gates[2 * warp] = p[i1];
        g_gates[2 * warp + 1] = p[i2];
        int q1 = atomicAdd(&g_counts[layer * 8 + i1], 1);
        g_lists[i1 * CAP + q1] = 2 * warp;
        int q2 = atomicAdd(&g_counts[layer * 8 + i2], 1);
        g_lists[i2 * CAP + q2] = 2 * warp + 1;
    }
}

__global__ void moe_combine_k(float* __restrict__ O)
{
    long i = (long)blockIdx.x * 256 + threadIdx.x;
    long tok = i >> 9; int d = (int)(i & 511);
    O[i] = g_Y[(tok * 2) * DMODEL + d] + g_Y[(tok * 2 + 1) * DMODEL + d];
}

__global__ void meanpool1_k(const float* __restrict__ X, float* __restrict__ part)
{
    int b = blockIdx.x, gg = blockIdx.y, t = threadIdx.x;
    #pragma unroll
    for (int j = 0; j < 2; j++) {
        int d = t + j * 256;
        float s = 0.f;
        #pragma unroll 4
        for (int i = 0; i < 32; i++)
            s += X[((size_t)b * 256 + gg * 32 + i) * 512 + d];
        part[((size_t)b * 8 + gg) * 512 + d] = s;
    }
}
__global__ void meanpool2_k(const float* __restrict__ part, float* __restrict__ fv)
{
    int b = blockIdx.x, d = threadIdx.x;
    float s = 0.f;
    #pragma unroll
    for (int gg = 0; gg < 8; gg++) s += part[((size_t)b * 8 + gg) * 512 + d];
    fv[b * 512 + d] = s * (1.f / 256.f);
}

__global__ void loss_k(float* __restrict__ out)
{
    float L = 0.f;
    for (int layer = 0; layer < 2; layer++) {
        float s = 0.f;
        for (int e = 0; e < 8; e++)
            s += ((float)g_counts[layer * 8 + e] * (1.f / NTOK)) * (g_imp[layer * 8 + e] * (1.f / NTOK));
        L += 8.f * s;
    }
    out[0] = L;
}

extern "C" void kernel_launch(void* const* d_in, const int* in_sizes, int n_in,
                              void* d_out, int out_size)
{
    const float* x = (const float*)d_in[0];
    const float* pe_w = (const float*)d_in[1];
    const float* pe_b = (const float*)d_in[2];
    const float* pos = (const float*)d_in[3];
    const float* ln1_g = (const float*)d_in[4]; const float* ln1_b = (const float*)d_in[5];
    const float* ln2_g = (const float*)d_in[6]; const float* ln2_b = (const float*)d_in[7];
    const float* ln3_g = (const float*)d_in[8]; const float* ln3_b = (const float*)d_in[9];
    const float* wq = (const float*)d_in[10]; const float* bq = (const float*)d_in[11];
    const float* wk = (const float*)d_in[12]; const float* bk = (const float*)d_in[13];
    const float* wv = (const float*)d_in[14]; const float* bv = (const float*)d_in[15];
    const float* wo = (const float*)d_in[16]; const float* bo = (const float*)d_in[17];
    const float* m1_rw = (const float*)d_in[18]; const float* m1_rb = (const float*)d_in[19];
    const float* m1_w1 = (const float*)d_in[20]; const float* m1_b1 = (const float*)d_in[21];
    const float* m1_w2 = (const float*)d_in[22]; const float* m1_b2 = (const float*)d_in[23];
    const float* m2_rw = (const float*)d_in[24]; const float* m2_rb = (const float*)d_in[25];
    const float* m2_w1 = (const float*)d_in[26]; const float* m2_b1 = (const float*)d_in[27];
    const float* m2_w2 = (const float*)d_in[28]; const float* m2_b2 = (const float*)d_in[29];
    const float* cls_w = (const float*)d_in[30]; const float* cls_b = (const float*)d_in[31];
    float* out = (float*)d_out;

    cudaFuncSetAttribute(gemm_mma<0>, cudaFuncAttributeMaxDynamicSharedMemorySize, DSMEM2);
    cudaFuncSetAttribute(gemm_mma<1>, cudaFuncAttributeMaxDynamicSharedMemorySize, DSMEM2);
    cudaFuncSetAttribute(gemm_mma<2>, cudaFuncAttributeMaxDynamicSharedMemorySize, DSMEM2);
    cudaFuncSetAttribute(gemm_mma<3>, cudaFuncAttributeMaxDynamicSharedMemorySize, DSMEM2);
    cudaFuncSetAttribute(gemm_mma<4>, cudaFuncAttributeMaxDynamicSharedMemorySize, DSMEM2);
    cudaFuncSetAttribute(gemm_mma<5>, cudaFuncAttributeMaxDynamicSharedMemorySize, DSMEM2);

    void *pP, *pE, *pL, *pQ, *pK, *pV, *pC, *pE2, *pX, *pO1, *pO2, *pA, *pH, *pY;
    void *tPE, *tQ, *tK, *tV, *tO, *tW1, *tW2;
    cudaGetSymbolAddress(&pP, g_patches); cudaGetSymbolAddress(&pE, g_e);
    cudaGetSymbolAddress(&pL, g_ln); cudaGetSymbolAddress(&pQ, g_q);
    cudaGetSymbolAddress(&pK, g_k); cudaGetSymbolAddress(&pV, g_v);
    cudaGetSymbolAddress(&pC, g_ctx); cudaGetSymbolAddress(&pE2, g_e2);
    cudaGetSymbolAddress(&pX, g_xm); cudaGetSymbolAddress(&pO1, g_o1);
    cudaGetSymbolAddress(&pO2, g_o2); cudaGetSymbolAddress(&pA, g_attn);
    cudaGetSymbolAddress(&pH, g_H); cudaGetSymbolAddress(&pY, g_Y);
    cudaGetSymbolAddress(&tPE, g_pewt); cudaGetSymbolAddress(&tQ, g_wqt);
    cudaGetSymbolAddress(&tK, g_wkt); cudaGetSymbolAddress(&tV, g_wvt);
    cudaGetSymbolAddress(&tO, g_wot); cudaGetSymbolAddress(&tW1, g_w1t);
    cudaGetSymbolAddress(&tW2, g_w2t);

    float* logits_out = out;
    float* fv_out = out + 16384;
    float* loss_out = out + 32768;
    float* attnw_out = out + 32769;

    zero_k<<<1, 32>>>();
    patchify_k<<<(NTOK * PDP + 255) / 256, 256>>>(x);
    transpose_k<<<dim3(19, 16), 256>>>(pe_w, (float*)tPE, PD, 512, PDP);
    transpose_k<<<dim3(16, 16), 256>>>(wq, (float*)tQ, 512, 512, 512);
    transpose_k<<<dim3(16, 16), 256>>>(wk, (float*)tK, 512, 512, 512);
    transpose_k<<<dim3(16, 16), 256>>>(wv, (float*)tV, 512, 512, 512);
    transpose_k<<<dim3(16, 16), 256>>>(wo, (float*)tO, 512, 512, 512);

    gemm_mma<2><<<dim3(64, 4), 256, DSMEM2>>>((const float*)pP, PDP, (const float*)tPE, PDP,
                                              (float*)pE, 512, PDP, 512, pe_b, pos, 0);
    layernorm_k<<<NTOK, 256>>>((const float*)pE, ln1_g, ln1_b, (float*)pL);
    gemm_mma<0><<<dim3(64, 4), 256, DSMEM2>>>((const float*)pL, 512, (const float*)tQ, 512,
                                              (float*)pQ, 512, 512, 512, bq, nullptr, 0);
    gemm_mma<0><<<dim3(64, 4), 256, DSMEM2>>>((const float*)pL, 512, (const float*)tK, 512,
                                              (float*)pK, 512, 512, 512, bk, nullptr, 0);
    gemm_mma<0><<<dim3(64, 4), 256, DSMEM2>>>((const float*)pL, 512, (const float*)tV, 512,
                                              (float*)pV, 512, 512, 512, bv, nullptr, 0);
    gemm_mma<5><<<dim3(2, 2, 256), 256, DSMEM2>>>((const float*)pQ, 512, (const float*)pK, 512,
                                                  (float*)pA, 256, 64, 256, nullptr, nullptr, 0);
    softmax256_k<<<65536, 256>>>((float*)pA);
    attn_mean_k<<<NTOK, 256>>>(attnw_out);
    attn_ctx_k<<<dim3(4, 256), 256>>>((const float*)pV);
    gemm_mma<1><<<dim3(64, 4), 256, DSMEM2>>>((const float*)pC, 512, (const float*)tO, 512,
                                              (float*)pE2, 512, 512, 512, bo, (const float*)pE, 0);

    // MoE layer 1
    layernorm_k<<<NTOK, 256>>>((const float*)pE2, ln2_g, ln2_b, (float*)pX);
    router_k<<<NTOK / 8, 256>>>((const float*)pX, m1_rw, m1_rb, 0);
    transpose_k<<<dim3(16, 64, 8), 256>>>(m1_w1, (float*)tW1, 512, 2048, 512);
    transpose_k<<<dim3(64, 16, 8), 256>>>(m1_w2, (float*)tW2, 2048, 512, 2048);
    gemm_mma<3><<<dim3(128, 16, 8), 256, DSMEM2>>>((const float*)pX, 512, (const float*)tW1, 512,
                                                   (float*)pH, 2048, 512, 2048, m1_b1, nullptr, 0);
    gemm_mma<4><<<dim3(128, 4, 8), 256, DSMEM2>>>((const float*)pH, 2048, (const float*)tW2, 2048,
                                                  (float*)pY, 512, 2048, 512, m1_b2, nullptr, 0);
    moe_combine_k<<<NTOK * DMODEL / 256, 256>>>((float*)pO1);

    // MoE layer 2
    layernorm_k<<<NTOK, 256>>>((const float*)pO1, ln3_g, ln3_b, (float*)pX);
    router_k<<<NTOK / 8, 256>>>((const float*)pX, m2_rw, m2_rb, 1);
    transpose_k<<<dim3(16, 64, 8), 256>>>(m2_w1, (float*)tW1, 512, 2048, 512);
    transpose_k<<<dim3(64, 16, 8), 256>>>(m2_w2, (float*)tW2, 2048, 512, 2048);
    gemm_mma<3><<<dim3(128, 16, 8), 256, DSMEM2>>>((const float*)pX, 512, (const float*)tW1, 512,
                                                   (float*)pH, 2048, 512, 2048, m2_b1, nullptr, 1);
    gemm_mma<4><<<dim3(128, 4, 8), 256, DSMEM2>>>((const float*)pH, 2048, (const float*)tW2, 2048,
                                                  (float*)pY, 512, 2048, 512, m2_b2, nullptr, 1);
    moe_combine_k<<<NTOK * DMODEL / 256, 256>>>((float*)pO2);

    meanpool1_k<<<dim3(32, 8), 256>>>((const float*)pO2, (float*)pP);
    meanpool2_k<<<32, 512>>>((const float*)pP, fv_out);
    gemm_nn<<<dim3(1, 8), 256>>>(fv_out, cls_w, logits_out, 32, 512, 512, cls_b);
    loss_k<<<1, 1>>>(loss_out);
}